// round 4
// baseline (speedup 1.0000x reference)
#include <cuda_runtime.h>
#include <math.h>
#include <stdint.h>

#define Gn 8
#define Hn 64
#define In 64
#define Bn 32
#define Tn 1000
#define ROWS (Bn * Tn)   // 32000

// Scratch: xp[((b*G+g)*T + t)*192 + j]  — sequential in t per (b,g)
__device__ float g_xp[(size_t)Bn * Gn * Tn * 192];

// ---------------- packed f32x2 helpers (sm_103a) ----------------
__device__ __forceinline__ uint64_t ffma2(uint64_t a, uint64_t b, uint64_t c) {
    uint64_t d;
    asm("fma.rn.f32x2 %0, %1, %2, %3;" : "=l"(d) : "l"(a), "l"(b), "l"(c));
    return d;
}
__device__ __forceinline__ uint64_t fadd2(uint64_t a, uint64_t b) {
    uint64_t d;
    asm("add.rn.f32x2 %0, %1, %2;" : "=l"(d) : "l"(a), "l"(b));
    return d;
}
__device__ __forceinline__ uint64_t pack2(float lo, float hi) {
    uint64_t d;
    asm("mov.b64 %0, {%1, %2};" : "=l"(d) : "f"(lo), "f"(hi));
    return d;
}
__device__ __forceinline__ float2 unpack2(uint64_t v) {
    float lo, hi;
    asm("mov.b64 {%0, %1}, %2;" : "=f"(lo), "=f"(hi) : "l"(v));
    return make_float2(lo, hi);
}
__device__ __forceinline__ float fsig(float x) {
    return __fdividef(1.f, 1.f + __expf(-x));
}

// ---------------------------------------------------------------------------
// Phase 1: xp = x @ Wih^T + bih  (per group; 64-row x 64-col tiles, f32x2)
// grid = (500, 8, 3), block = 256   [unchanged from R2 — measured 222us]
// ---------------------------------------------------------------------------
__global__ void __launch_bounds__(256) xproj_kernel(const float* __restrict__ x,
                                                    const float* __restrict__ Wih,
                                                    const float* __restrict__ bih)
{
    __shared__ __align__(16) float xs[64][68];  // [k][row]
    __shared__ __align__(16) float ws[64][68];  // [k][col]

    const int tile = blockIdx.x;
    const int g    = blockIdx.y;
    const int sec  = blockIdx.z;
    const int tid  = threadIdx.x;

    for (int idx = tid; idx < 64 * 16; idx += 256) {
        int row = idx >> 4;
        int k4  = (idx & 15) * 4;
        int n   = tile * 64 + row;
        float4 v = *(const float4*)&x[(size_t)n * (Gn * In) + g * In + k4];
        xs[k4 + 0][row] = v.x;
        xs[k4 + 1][row] = v.y;
        xs[k4 + 2][row] = v.z;
        xs[k4 + 3][row] = v.w;
    }
    for (int idx = tid; idx < 64 * 16; idx += 256) {
        int j  = idx >> 4;
        int k4 = (idx & 15) * 4;
        float4 v = *(const float4*)&Wih[((size_t)g * 192 + sec * 64 + j) * In + k4];
        ws[k4 + 0][j] = v.x;
        ws[k4 + 1][j] = v.y;
        ws[k4 + 2][j] = v.z;
        ws[k4 + 3][j] = v.w;
    }
    __syncthreads();

    const int tx = tid & 15;
    const int ty = tid >> 4;
    const int r0 = ty * 4;
    const int c0 = tx * 4;

    uint64_t A01[4], A23[4];
#pragma unroll
    for (int i = 0; i < 4; i++) { A01[i] = 0ull; A23[i] = 0ull; }

#pragma unroll 8
    for (int k = 0; k < 64; k++) {
        float4 av = *(const float4*)&xs[k][r0];
        ulonglong2 wv = *(const ulonglong2*)&ws[k][c0];
        uint64_t a0 = pack2(av.x, av.x);
        uint64_t a1 = pack2(av.y, av.y);
        uint64_t a2 = pack2(av.z, av.z);
        uint64_t a3 = pack2(av.w, av.w);
        A01[0] = ffma2(a0, wv.x, A01[0]);  A23[0] = ffma2(a0, wv.y, A23[0]);
        A01[1] = ffma2(a1, wv.x, A01[1]);  A23[1] = ffma2(a1, wv.y, A23[1]);
        A01[2] = ffma2(a2, wv.x, A01[2]);  A23[2] = ffma2(a2, wv.y, A23[2]);
        A01[3] = ffma2(a3, wv.x, A01[3]);  A23[3] = ffma2(a3, wv.y, A23[3]);
    }

    float4 bv = *(const float4*)&bih[g * 192 + sec * 64 + c0];
#pragma unroll
    for (int i = 0; i < 4; i++) {
        int n = tile * 64 + r0 + i;
        int b = n / Tn;
        int t = n - b * Tn;
        size_t o = ((size_t)(b * Gn + g) * Tn + t) * 192 + sec * 64 + c0;
        float2 lo = unpack2(A01[i]);
        float2 hi = unpack2(A23[i]);
        float4 v;
        v.x = lo.x + bv.x;
        v.y = lo.y + bv.y;
        v.z = hi.x + bv.z;
        v.w = hi.y + bv.w;
        *(float4*)&g_xp[o] = v;
    }
}

// ---------------------------------------------------------------------------
// Phase 2: scan. One block per (b,g). 256 threads: thread (k=j/4, s=j%4)
// computes K-slice s of ALL THREE gate rows for h-index k, butterfly-reduces
// over the 4 lanes of the group, then computes the gates locally.
// h double-buffered in smem -> ONE __syncthreads per step.
// grid = 256, block = 256
// ---------------------------------------------------------------------------
__global__ void __launch_bounds__(256) scan_kernel(const float* __restrict__ h0,
                                                   const float* __restrict__ Whh,
                                                   const float* __restrict__ bhh,
                                                   float* __restrict__ out)
{
    const int bidx = blockIdx.x;
    const int b = bidx >> 3;
    const int g = bidx & 7;
    const int j = threadIdx.x;
    const int k = j >> 2;   // 0..63  (h index)
    const int s = j & 3;    // 0..3   (K-slice)

    __shared__ __align__(16) float hbuf0[64];
    __shared__ __align__(16) float hbuf1[64];

    // Weight slices: rows k (r), 64+k (z), 128+k (n); columns [16s, 16s+16)
    uint64_t wr[8], wz[8], wn[8];
    {
        const uint64_t* p;
        p = (const uint64_t*)&Whh[((size_t)g * 192 + k) * Hn + s * 16];
#pragma unroll
        for (int i = 0; i < 8; i++) wr[i] = p[i];
        p = (const uint64_t*)&Whh[((size_t)g * 192 + 64 + k) * Hn + s * 16];
#pragma unroll
        for (int i = 0; i < 8; i++) wz[i] = p[i];
        p = (const uint64_t*)&Whh[((size_t)g * 192 + 128 + k) * Hn + s * 16];
#pragma unroll
        for (int i = 0; i < 8; i++) wn[i] = p[i];
    }
    // Folded bias: lane s folds the bias of gate s (s==3 folds nothing)
    const float bias = (s == 0) ? bhh[g * 192 + k]
                     : (s == 1) ? bhh[g * 192 + 64 + k]
                     : (s == 2) ? bhh[g * 192 + 128 + k] : 0.f;

    if (j < 64) hbuf0[j] = h0[((size_t)g * Bn + b) * Hn + j];

    const float* xbase = &g_xp[((size_t)(b * Gn + g) * Tn) * 192];
    const float* xfold_p = (s == 0) ? (xbase + k) : (xbase + 64 + k);  // s>=2 unused
    const bool   do_fold = (s < 2);
    const float* xn_p = xbase + 128 + k;
    float* outp = out + (size_t)b * Tn * (Gn * Hn) + g * Hn + k;

    // prefetch ring, depth 2
    float xf0 = 0.f, xf1 = 0.f;
    if (do_fold) { xf0 = __ldcs(xfold_p); xf1 = __ldcs(xfold_p + 192); }
    float xn0 = __ldcs(xn_p);
    float xn1 = __ldcs(xn_p + 192);

    __syncthreads();

#define STEP(HR, HW, T_, XF_, XN_)                                            \
    {                                                                         \
        const ulonglong2* hp = (const ulonglong2*)((HR) + s * 16);            \
        ulonglong2 hq0 = hp[0], hq1 = hp[1], hq2 = hp[2], hq3 = hp[3];        \
        float hk = (HR)[k];                                                   \
        float fold = bias + (XF_);                                            \
        uint64_t fp = pack2(fold, 0.f);                                       \
        uint64_t ar0 = (s == 0) ? fp : 0ull, ar1 = 0ull;                      \
        uint64_t az0 = (s == 1) ? fp : 0ull, az1 = 0ull;                      \
        uint64_t an0 = (s >= 2) ? fp : 0ull, an1 = 0ull;                      \
        uint64_t h64[8] = {hq0.x, hq0.y, hq1.x, hq1.y,                        \
                           hq2.x, hq2.y, hq3.x, hq3.y};                       \
        _Pragma("unroll")                                                     \
        for (int i = 0; i < 8; i += 2) {                                      \
            ar0 = ffma2(wr[i], h64[i], ar0);                                  \
            ar1 = ffma2(wr[i + 1], h64[i + 1], ar1);                          \
            az0 = ffma2(wz[i], h64[i], az0);                                  \
            az1 = ffma2(wz[i + 1], h64[i + 1], az1);                          \
            an0 = ffma2(wn[i], h64[i], an0);                                  \
            an1 = ffma2(wn[i + 1], h64[i + 1], an1);                          \
        }                                                                     \
        float2 fr = unpack2(fadd2(ar0, ar1));                                 \
        float2 fz = unpack2(fadd2(az0, az1));                                 \
        float2 fn = unpack2(fadd2(an0, an1));                                 \
        float vr = fr.x + fr.y;                                               \
        float vz = fz.x + fz.y;                                               \
        float vn = fn.x + fn.y;                                               \
        vr += __shfl_xor_sync(0xFFFFFFFFu, vr, 1);                            \
        vz += __shfl_xor_sync(0xFFFFFFFFu, vz, 1);                            \
        vn += __shfl_xor_sync(0xFFFFFFFFu, vn, 1);                            \
        vr += __shfl_xor_sync(0xFFFFFFFFu, vr, 2);                            \
        vz += __shfl_xor_sync(0xFFFFFFFFu, vz, 2);                            \
        vn += __shfl_xor_sync(0xFFFFFFFFu, vn, 2);                            \
        float rr = fsig(vr);                                                  \
        float zz = fsig(vz);                                                  \
        float aa = (XN_) + rr * vn;                                           \
        float nn = __fmaf_rn(2.f, fsig(2.f * aa), -1.f);                      \
        float hn = nn + zz * (hk - nn);                                       \
        if (s == 0) {                                                         \
            (HW)[k] = hn;                                                     \
            __stcs(&outp[(size_t)(T_) * (Gn * Hn)], hn);                      \
        }                                                                     \
        __syncthreads();                                                      \
    }

    for (int t = 0; t < Tn; t += 2) {
        STEP(hbuf0, hbuf1, t, xf0, xn0);
        {
            size_t o = (size_t)min(t + 2, Tn - 1) * 192;
            if (do_fold) xf0 = __ldcs(xfold_p + o);
            xn0 = __ldcs(xn_p + o);
        }
        STEP(hbuf1, hbuf0, t + 1, xf1, xn1);
        {
            size_t o = (size_t)min(t + 3, Tn - 1) * 192;
            if (do_fold) xf1 = __ldcs(xfold_p + o);
            xn1 = __ldcs(xn_p + o);
        }
    }
#undef STEP

    // Tn even -> final h landed in hbuf0 (written by last STEP, after barrier)
    if (j < 64) {
        out[(size_t)Bn * Tn * (Gn * Hn) + ((size_t)g * Bn + b) * Hn + j] = hbuf0[j];
    }
}

// ---------------------------------------------------------------------------
extern "C" void kernel_launch(void* const* d_in, const int* in_sizes, int n_in,
                              void* d_out, int out_size)
{
    const float* x   = (const float*)d_in[0];
    const float* h0  = (const float*)d_in[1];
    const float* Wih = (const float*)d_in[2];
    const float* Whh = (const float*)d_in[3];
    const float* bih = (const float*)d_in[4];
    const float* bhh = (const float*)d_in[5];
    float* out = (float*)d_out;

    dim3 g1(ROWS / 64, Gn, 3);
    xproj_kernel<<<g1, 256>>>(x, Wih, bih);

    scan_kernel<<<Bn * Gn, 256>>>(h0, Whh, bhh, out);
}

// round 5
// speedup vs baseline: 1.0026x; 1.0026x over previous
#include <cuda_runtime.h>
#include <math.h>
#include <stdint.h>

#define Gn 8
#define Hn 64
#define In 64
#define Bn 32
#define Tn 1000
#define ROWS (Bn * Tn)   // 32000

// Scratch: xp[((b*G+g)*T + t)*192 + j]  — sequential in t per (b,g)
__device__ float g_xp[(size_t)Bn * Gn * Tn * 192];

// ---------------- packed f32x2 helpers (sm_103a) ----------------
__device__ __forceinline__ uint64_t ffma2(uint64_t a, uint64_t b, uint64_t c) {
    uint64_t d;
    asm("fma.rn.f32x2 %0, %1, %2, %3;" : "=l"(d) : "l"(a), "l"(b), "l"(c));
    return d;
}
__device__ __forceinline__ uint64_t fadd2(uint64_t a, uint64_t b) {
    uint64_t d;
    asm("add.rn.f32x2 %0, %1, %2;" : "=l"(d) : "l"(a), "l"(b));
    return d;
}
__device__ __forceinline__ uint64_t pack2(float lo, float hi) {
    uint64_t d;
    asm("mov.b64 %0, {%1, %2};" : "=l"(d) : "f"(lo), "f"(hi));
    return d;
}
__device__ __forceinline__ float2 unpack2(uint64_t v) {
    float lo, hi;
    asm("mov.b64 {%0, %1}, %2;" : "=f"(lo), "=f"(hi) : "l"(v));
    return make_float2(lo, hi);
}
__device__ __forceinline__ float fsig(float x) {
    return __fdividef(1.f, 1.f + __expf(-x));
}

// ---------------------------------------------------------------------------
// Phase 1: xp = x @ Wih^T + bih  (per group; 64-row x 64-col tiles, f32x2)
// grid = (500, 8, 3), block = 256  [unchanged — near fp32 roofline, ~222us]
// ---------------------------------------------------------------------------
__global__ void __launch_bounds__(256) xproj_kernel(const float* __restrict__ x,
                                                    const float* __restrict__ Wih,
                                                    const float* __restrict__ bih)
{
    __shared__ __align__(16) float xs[64][68];  // [k][row]
    __shared__ __align__(16) float ws[64][68];  // [k][col]

    const int tile = blockIdx.x;
    const int g    = blockIdx.y;
    const int sec  = blockIdx.z;
    const int tid  = threadIdx.x;

    for (int idx = tid; idx < 64 * 16; idx += 256) {
        int row = idx >> 4;
        int k4  = (idx & 15) * 4;
        int n   = tile * 64 + row;
        float4 v = *(const float4*)&x[(size_t)n * (Gn * In) + g * In + k4];
        xs[k4 + 0][row] = v.x;
        xs[k4 + 1][row] = v.y;
        xs[k4 + 2][row] = v.z;
        xs[k4 + 3][row] = v.w;
    }
    for (int idx = tid; idx < 64 * 16; idx += 256) {
        int j  = idx >> 4;
        int k4 = (idx & 15) * 4;
        float4 v = *(const float4*)&Wih[((size_t)g * 192 + sec * 64 + j) * In + k4];
        ws[k4 + 0][j] = v.x;
        ws[k4 + 1][j] = v.y;
        ws[k4 + 2][j] = v.z;
        ws[k4 + 3][j] = v.w;
    }
    __syncthreads();

    const int tx = tid & 15;
    const int ty = tid >> 4;
    const int r0 = ty * 4;
    const int c0 = tx * 4;

    uint64_t A01[4], A23[4];
#pragma unroll
    for (int i = 0; i < 4; i++) { A01[i] = 0ull; A23[i] = 0ull; }

#pragma unroll 8
    for (int k = 0; k < 64; k++) {
        float4 av = *(const float4*)&xs[k][r0];
        ulonglong2 wv = *(const ulonglong2*)&ws[k][c0];
        uint64_t a0 = pack2(av.x, av.x);
        uint64_t a1 = pack2(av.y, av.y);
        uint64_t a2 = pack2(av.z, av.z);
        uint64_t a3 = pack2(av.w, av.w);
        A01[0] = ffma2(a0, wv.x, A01[0]);  A23[0] = ffma2(a0, wv.y, A23[0]);
        A01[1] = ffma2(a1, wv.x, A01[1]);  A23[1] = ffma2(a1, wv.y, A23[1]);
        A01[2] = ffma2(a2, wv.x, A01[2]);  A23[2] = ffma2(a2, wv.y, A23[2]);
        A01[3] = ffma2(a3, wv.x, A01[3]);  A23[3] = ffma2(a3, wv.y, A23[3]);
    }

    float4 bv = *(const float4*)&bih[g * 192 + sec * 64 + c0];
#pragma unroll
    for (int i = 0; i < 4; i++) {
        int n = tile * 64 + r0 + i;
        int b = n / Tn;
        int t = n - b * Tn;
        size_t o = ((size_t)(b * Gn + g) * Tn + t) * 192 + sec * 64 + c0;
        float2 lo = unpack2(A01[i]);
        float2 hi = unpack2(A23[i]);
        float4 v;
        v.x = lo.x + bv.x;
        v.y = lo.y + bv.y;
        v.z = hi.x + bv.z;
        v.w = hi.y + bv.w;
        *(float4*)&g_xp[o] = v;
    }
}

// ---------------------------------------------------------------------------
// Phase 2: scan. 384-thread block = TWO independent R2-style instances:
//   threads   0..191 -> batch b = 2*pair     (inst 0)
//   threads 192..383 -> batch b = 2*pair + 1 (inst 1)
// Each instance: thread j owns gate-row j of Whh in registers; h in smem;
// gate threads (j<64) keep h[j] in a register and prefetch x directly.
// grid = 128 (one block per SM), block = 384
// ---------------------------------------------------------------------------
__global__ void __launch_bounds__(384) scan_kernel(const float* __restrict__ h0,
                                                   const float* __restrict__ Whh,
                                                   const float* __restrict__ bhh,
                                                   float* __restrict__ out)
{
    const int inst = (threadIdx.x >= 192) ? 1 : 0;
    const int j    = threadIdx.x - inst * 192;
    const int pair = blockIdx.x >> 3;        // 0..15
    const int g    = blockIdx.x & 7;
    const int b    = pair * 2 + inst;

    __shared__ __align__(16) float h_sh[2][64];
    __shared__ __align__(16) float gh_sh[2][192];
    float* hS  = h_sh[inst];
    float* ghS = gh_sh[inst];

    // Whh row j as 16 packed-pair registers
    ulonglong2 w[16];
    const ulonglong2* wrow = (const ulonglong2*)&Whh[((size_t)g * 192 + j) * Hn];
#pragma unroll
    for (int q = 0; q < 16; q++) w[q] = wrow[q];
    const float bj = bhh[g * 192 + j];

    const bool is_gate = (j < 64);
    float hreg = 0.f;
    if (is_gate) {
        hreg = h0[((size_t)g * Bn + b) * Hn + j];
        hS[j] = hreg;
    }

    const float* xbase = &g_xp[((size_t)(b * Gn + g) * Tn) * 192];
    float* outp = out + (size_t)b * Tn * (Gn * Hn) + g * Hn + j;  // valid for j<64

    // depth-2 register prefetch ring of (xr, xz, xn) — gate threads only
    float xr0 = 0.f, xz0 = 0.f, xn0 = 0.f, xr1 = 0.f, xz1 = 0.f, xn1 = 0.f;
    if (is_gate) {
        xr0 = __ldcs(xbase + j);        xz0 = __ldcs(xbase + 64 + j);        xn0 = __ldcs(xbase + 128 + j);
        xr1 = __ldcs(xbase + 192 + j);  xz1 = __ldcs(xbase + 192 + 64 + j);  xn1 = __ldcs(xbase + 192 + 128 + j);
    }

#define STEP(T_, XR_, XZ_, XN_)                                               \
    {                                                                         \
        __syncthreads();   /* hS ready (init or previous gates) */            \
        uint64_t A0 = pack2(bj, 0.f), A1 = 0ull, A2 = 0ull, A3 = 0ull;        \
        const ulonglong2* h2 = (const ulonglong2*)hS;                         \
        _Pragma("unroll")                                                     \
        for (int q = 0; q < 16; q += 2) {                                     \
            ulonglong2 ha = h2[q];                                            \
            ulonglong2 hb = h2[q + 1];                                        \
            A0 = ffma2(w[q].x,     ha.x, A0);                                 \
            A1 = ffma2(w[q].y,     ha.y, A1);                                 \
            A2 = ffma2(w[q + 1].x, hb.x, A2);                                 \
            A3 = ffma2(w[q + 1].y, hb.y, A3);                                 \
        }                                                                     \
        float2 s_ = unpack2(fadd2(fadd2(A0, A1), fadd2(A2, A3)));             \
        ghS[j] = s_.x + s_.y;                                                 \
        __syncthreads();   /* ghS ready */                                    \
        if (is_gate) {                                                        \
            float rr = fsig((XR_) + ghS[j]);                                  \
            float zz = fsig((XZ_) + ghS[64 + j]);                             \
            float aa = (XN_) + rr * ghS[128 + j];                             \
            float nn = __fmaf_rn(2.f, fsig(2.f * aa), -1.f);                  \
            float hn = nn + zz * (hreg - nn);                                 \
            hreg = hn;                                                        \
            hS[j] = hn;                                                       \
            __stcs(&outp[(size_t)(T_) * (Gn * Hn)], hn);                      \
        }                                                                     \
    }

    for (int t = 0; t < Tn; t += 2) {
        STEP(t, xr0, xz0, xn0);
        if (is_gate) {
            size_t o = (size_t)min(t + 2, Tn - 1) * 192;
            xr0 = __ldcs(xbase + o + j);
            xz0 = __ldcs(xbase + o + 64 + j);
            xn0 = __ldcs(xbase + o + 128 + j);
        }
        STEP(t + 1, xr1, xz1, xn1);
        if (is_gate) {
            size_t o = (size_t)min(t + 3, Tn - 1) * 192;
            xr1 = __ldcs(xbase + o + j);
            xz1 = __ldcs(xbase + o + 64 + j);
            xn1 = __ldcs(xbase + o + 128 + j);
        }
    }
#undef STEP

    if (is_gate) {
        // final hidden state from register — no sync needed
        out[(size_t)Bn * Tn * (Gn * Hn) + ((size_t)g * Bn + b) * Hn + j] = hreg;
    }
}

// ---------------------------------------------------------------------------
extern "C" void kernel_launch(void* const* d_in, const int* in_sizes, int n_in,
                              void* d_out, int out_size)
{
    const float* x   = (const float*)d_in[0];
    const float* h0  = (const float*)d_in[1];
    const float* Wih = (const float*)d_in[2];
    const float* Whh = (const float*)d_in[3];
    const float* bih = (const float*)d_in[4];
    const float* bhh = (const float*)d_in[5];
    float* out = (float*)d_out;

    dim3 g1(ROWS / 64, Gn, 3);
    xproj_kernel<<<g1, 256>>>(x, Wih, bih);

    scan_kernel<<<(Bn / 2) * Gn, 384>>>(h0, Whh, bhh, out);
}

// round 6
// speedup vs baseline: 1.1901x; 1.1871x over previous
#include <cuda_runtime.h>
#include <math.h>
#include <stdint.h>

#define Gn 8
#define Hn 64
#define In 64
#define Bn 32
#define Tn 1000
#define ROWS (Bn * Tn)   // 32000

// Scratch: xp[((b*G+g)*T + t)*192 + j]  — sequential in t per (b,g)
__device__ float g_xp[(size_t)Bn * Gn * Tn * 192];

// ---------------- packed f32x2 helpers (sm_103a) ----------------
__device__ __forceinline__ uint64_t ffma2(uint64_t a, uint64_t b, uint64_t c) {
    uint64_t d;
    asm("fma.rn.f32x2 %0, %1, %2, %3;" : "=l"(d) : "l"(a), "l"(b), "l"(c));
    return d;
}
__device__ __forceinline__ uint64_t fadd2(uint64_t a, uint64_t b) {
    uint64_t d;
    asm("add.rn.f32x2 %0, %1, %2;" : "=l"(d) : "l"(a), "l"(b));
    return d;
}
__device__ __forceinline__ uint64_t pack2(float lo, float hi) {
    uint64_t d;
    asm("mov.b64 %0, {%1, %2};" : "=l"(d) : "f"(lo), "f"(hi));
    return d;
}
__device__ __forceinline__ float2 unpack2(uint64_t v) {
    float lo, hi;
    asm("mov.b64 {%0, %1}, %2;" : "=f"(lo), "=f"(hi) : "l"(v));
    return make_float2(lo, hi);
}
__device__ __forceinline__ float fsig(float x) {
    return __fdividef(1.f, 1.f + __expf(-x));
}

// ---------------------------------------------------------------------------
// Phase 1: xp = x @ Wih^T + bih  (per group; 64-row x 64-col tiles, f32x2)
// grid = (500, 8, 3), block = 256  [unchanged — ~222us]
// ---------------------------------------------------------------------------
__global__ void __launch_bounds__(256) xproj_kernel(const float* __restrict__ x,
                                                    const float* __restrict__ Wih,
                                                    const float* __restrict__ bih)
{
    __shared__ __align__(16) float xs[64][68];  // [k][row]
    __shared__ __align__(16) float ws[64][68];  // [k][col]

    const int tile = blockIdx.x;
    const int g    = blockIdx.y;
    const int sec  = blockIdx.z;
    const int tid  = threadIdx.x;

    for (int idx = tid; idx < 64 * 16; idx += 256) {
        int row = idx >> 4;
        int k4  = (idx & 15) * 4;
        int n   = tile * 64 + row;
        float4 v = *(const float4*)&x[(size_t)n * (Gn * In) + g * In + k4];
        xs[k4 + 0][row] = v.x;
        xs[k4 + 1][row] = v.y;
        xs[k4 + 2][row] = v.z;
        xs[k4 + 3][row] = v.w;
    }
    for (int idx = tid; idx < 64 * 16; idx += 256) {
        int j  = idx >> 4;
        int k4 = (idx & 15) * 4;
        float4 v = *(const float4*)&Wih[((size_t)g * 192 + sec * 64 + j) * In + k4];
        ws[k4 + 0][j] = v.x;
        ws[k4 + 1][j] = v.y;
        ws[k4 + 2][j] = v.z;
        ws[k4 + 3][j] = v.w;
    }
    __syncthreads();

    const int tx = tid & 15;
    const int ty = tid >> 4;
    const int r0 = ty * 4;
    const int c0 = tx * 4;

    uint64_t A01[4], A23[4];
#pragma unroll
    for (int i = 0; i < 4; i++) { A01[i] = 0ull; A23[i] = 0ull; }

#pragma unroll 8
    for (int k = 0; k < 64; k++) {
        float4 av = *(const float4*)&xs[k][r0];
        ulonglong2 wv = *(const ulonglong2*)&ws[k][c0];
        uint64_t a0 = pack2(av.x, av.x);
        uint64_t a1 = pack2(av.y, av.y);
        uint64_t a2 = pack2(av.z, av.z);
        uint64_t a3 = pack2(av.w, av.w);
        A01[0] = ffma2(a0, wv.x, A01[0]);  A23[0] = ffma2(a0, wv.y, A23[0]);
        A01[1] = ffma2(a1, wv.x, A01[1]);  A23[1] = ffma2(a1, wv.y, A23[1]);
        A01[2] = ffma2(a2, wv.x, A01[2]);  A23[2] = ffma2(a2, wv.y, A23[2]);
        A01[3] = ffma2(a3, wv.x, A01[3]);  A23[3] = ffma2(a3, wv.y, A23[3]);
    }

    float4 bv = *(const float4*)&bih[g * 192 + sec * 64 + c0];
#pragma unroll
    for (int i = 0; i < 4; i++) {
        int n = tile * 64 + r0 + i;
        int b = n / Tn;
        int t = n - b * Tn;
        size_t o = ((size_t)(b * Gn + g) * Tn + t) * 192 + sec * 64 + c0;
        float2 lo = unpack2(A01[i]);
        float2 hi = unpack2(A23[i]);
        float4 v;
        v.x = lo.x + bv.x;
        v.y = lo.y + bv.y;
        v.z = hi.x + bv.z;
        v.w = hi.y + bv.w;
        *(float4*)&g_xp[o] = v;
    }
}

// ---------------------------------------------------------------------------
// Phase 2: scan. Block = 256 threads = 2 independent instances (named bars).
// Instance: 128 threads; pair (2m, 2m+1) owns h-index m. Lane `half` holds
// K-slice [32*half, 32*half+32) of gate rows r,z,n in registers (48 ffma2),
// reduces with one shfl_xor(1) per gate, computes gates locally.
// ONE named barrier per step; h double-buffered in smem.
// grid = 128, block = 256
// ---------------------------------------------------------------------------
__global__ void __launch_bounds__(256) scan_kernel(const float* __restrict__ h0,
                                                   const float* __restrict__ Whh,
                                                   const float* __restrict__ bhh,
                                                   float* __restrict__ out)
{
    const int inst  = threadIdx.x >> 7;       // 0 or 1
    const int tid_i = threadIdx.x & 127;
    const int m     = tid_i >> 1;             // h index 0..63
    const int half  = tid_i & 1;              // K-slice selector
    const int pair  = blockIdx.x >> 3;        // 0..15
    const int g     = blockIdx.x & 7;
    const int b     = pair * 2 + inst;
    const int barid = 1 + inst;

    __shared__ __align__(16) float h_sh[2][2][64];  // [inst][buf][64]
    float* hb0 = h_sh[inst][0];
    float* hb1 = h_sh[inst][1];

#define IBAR() asm volatile("bar.sync %0, 128;" :: "r"(barid) : "memory")

    // Weight slices: 16 u64 (32 floats) per gate row
    uint64_t wr[16], wz[16], wn[16];
    {
        const uint64_t* p;
        p = (const uint64_t*)&Whh[((size_t)g * 192 + m) * Hn + half * 32];
#pragma unroll
        for (int i = 0; i < 16; i++) wr[i] = p[i];
        p = (const uint64_t*)&Whh[((size_t)g * 192 + 64 + m) * Hn + half * 32];
#pragma unroll
        for (int i = 0; i < 16; i++) wz[i] = p[i];
        p = (const uint64_t*)&Whh[((size_t)g * 192 + 128 + m) * Hn + half * 32];
#pragma unroll
        for (int i = 0; i < 16; i++) wn[i] = p[i];
    }
    // lane0 folds br (+xr) into its r-partial and bn into its n-partial;
    // lane1 folds bz (+xz) into its z-partial.
    const float bias_rz = half ? bhh[g * 192 + 64 + m] : bhh[g * 192 + m];
    const float bias_n  = half ? 0.f : bhh[g * 192 + 128 + m];

    float hreg = h0[((size_t)g * Bn + b) * Hn + m];
    if (half == 0) hb0[m] = hreg;

    const float* xbase = &g_xp[((size_t)(b * Gn + g) * Tn) * 192];
    const float* xf_p  = xbase + (half ? (64 + m) : m);
    const float* xn_p  = xbase + 128 + m;
    float* outp = out + (size_t)b * Tn * (Gn * Hn) + g * Hn + m;

    // depth-2 prefetch ring
    float xf0 = __ldcs(xf_p);        float xn0 = __ldcs(xn_p);
    float xf1 = __ldcs(xf_p + 192);  float xn1 = __ldcs(xn_p + 192);

#define STEP(HR, HW, T_, XF_, XN_)                                            \
    {                                                                         \
        IBAR();  /* previous step's h writes visible; WAR safe via dbl-buf */ \
        const ulonglong2* hp = (const ulonglong2*)((HR) + half * 32);         \
        ulonglong2 q0 = hp[0], q1 = hp[1], q2 = hp[2], q3 = hp[3];            \
        uint64_t hh[8] = {q0.x, q0.y, q1.x, q1.y, q2.x, q2.y, q3.x, q3.y};    \
        float foldv = bias_rz + (XF_);                                        \
        uint64_t fp = pack2(foldv, 0.f);                                      \
        uint64_t ar0 = half ? 0ull : fp, ar1 = 0ull;                          \
        uint64_t az0 = half ? fp : 0ull, az1 = 0ull;                          \
        uint64_t an0 = pack2(bias_n, 0.f), an1 = 0ull;                        \
        _Pragma("unroll")                                                     \
        for (int i = 0; i < 8; i += 2) {                                      \
            ar0 = ffma2(wr[2 * i],     hh[i],     ar0);                       \
            ar1 = ffma2(wr[2 * i + 2], hh[i + 1], ar1);                       \
            az0 = ffma2(wz[2 * i],     hh[i],     az0);                       \
            az1 = ffma2(wz[2 * i + 2], hh[i + 1], az1);                       \
            an0 = ffma2(wn[2 * i],     hh[i],     an0);                       \
            an1 = ffma2(wn[2 * i + 2], hh[i + 1], an1);                       \
        }                                                                     \
        /* odd u64 chunks (hh holds 8 of 16; reload remaining) */             \
        ulonglong2 q4 = hp[4], q5 = hp[5], q6 = hp[6], q7 = hp[7];            \
        uint64_t hg[8] = {q4.x, q4.y, q5.x, q5.y, q6.x, q6.y, q7.x, q7.y};    \
        _Pragma("unroll")                                                     \
        for (int i = 0; i < 8; i += 2) {                                      \
            ar0 = ffma2(wr[2 * i + 8],  hg[i],     ar0);                      \
            ar1 = ffma2(wr[2 * i + 10], hg[i + 1], ar1);                      \
            az0 = ffma2(wz[2 * i + 8],  hg[i],     az0);                      \
            az1 = ffma2(wz[2 * i + 10], hg[i + 1], az1);                      \
            an0 = ffma2(wn[2 * i + 8],  hg[i],     an0);                      \
            an1 = ffma2(wn[2 * i + 10], hg[i + 1], an1);                      \
        }                                                                     \
        float2 fr = unpack2(fadd2(ar0, ar1));                                 \
        float2 fz = unpack2(fadd2(az0, az1));                                 \
        float2 fn = unpack2(fadd2(an0, an1));                                 \
        float vr = fr.x + fr.y;                                               \
        float vz = fz.x + fz.y;                                               \
        float vn = fn.x + fn.y;                                               \
        vr += __shfl_xor_sync(0xFFFFFFFFu, vr, 1);                            \
        vz += __shfl_xor_sync(0xFFFFFFFFu, vz, 1);                            \
        vn += __shfl_xor_sync(0xFFFFFFFFu, vn, 1);                            \
        float rr = fsig(vr);                                                  \
        float zz = fsig(vz);                                                  \
        float aa = (XN_) + rr * vn;                                           \
        float nn = __fmaf_rn(2.f, fsig(2.f * aa), -1.f);                      \
        float hn = nn + zz * (hreg - nn);                                     \
        hreg = hn;                                                            \
        if (half == 0) {                                                      \
            (HW)[m] = hn;                                                     \
            __stcs(&outp[(size_t)(T_) * (Gn * Hn)], hn);                      \
        }                                                                     \
    }

    // NOTE on wr indexing above: wr[] holds 16 u64 in order; the two loops
    // consume even-indexed (0,2,..,14 via 2*i/2*i+2) then odd-start (8..15
    // region) — mapping is consistent because hh/hg are the matching h chunks:
    // loop1 uses w chunks {0,2,4,6} & {1,3,5,7}? To avoid subtle mis-pairing,
    // the indices are arranged so w-chunk c multiplies h-chunk c:
    //   loop1: i=0: wr[0]*hh[0], wr[2]*hh[1] ... -> w chunks 0,2,4,6 with h 0,1,2,3
    // That is WRONG pairing unless h chunks are reordered. See fix below.
#undef STEP

    // ---- corrected STEP (w-chunk c pairs with h-chunk c) ----
#define STEP2(HR, HW, T_, XF_, XN_)                                           \
    {                                                                         \
        IBAR();                                                               \
        const uint64_t* hp = (const uint64_t*)((HR) + half * 32);             \
        float foldv = bias_rz + (XF_);                                        \
        uint64_t fp = pack2(foldv, 0.f);                                      \
        uint64_t ar0 = half ? 0ull : fp, ar1 = 0ull;                          \
        uint64_t az0 = half ? fp : 0ull, az1 = 0ull;                          \
        uint64_t an0 = pack2(bias_n, 0.f), an1 = 0ull;                        \
        _Pragma("unroll")                                                     \
        for (int i = 0; i < 16; i += 2) {                                     \
            uint64_t h0v = hp[i];                                             \
            uint64_t h1v = hp[i + 1];                                         \
            ar0 = ffma2(wr[i],     h0v, ar0);                                 \
            ar1 = ffma2(wr[i + 1], h1v, ar1);                                 \
            az0 = ffma2(wz[i],     h0v, az0);                                 \
            az1 = ffma2(wz[i + 1], h1v, az1);                                 \
            an0 = ffma2(wn[i],     h0v, an0);                                 \
            an1 = ffma2(wn[i + 1], h1v, an1);                                 \
        }                                                                     \
        float2 fr = unpack2(fadd2(ar0, ar1));                                 \
        float2 fz = unpack2(fadd2(az0, az1));                                 \
        float2 fn = unpack2(fadd2(an0, an1));                                 \
        float vr = fr.x + fr.y;                                               \
        float vz = fz.x + fz.y;                                               \
        float vn = fn.x + fn.y;                                               \
        vr += __shfl_xor_sync(0xFFFFFFFFu, vr, 1);                            \
        vz += __shfl_xor_sync(0xFFFFFFFFu, vz, 1);                            \
        vn += __shfl_xor_sync(0xFFFFFFFFu, vn, 1);                            \
        float rr = fsig(vr);                                                  \
        float zz = fsig(vz);                                                  \
        float aa = (XN_) + rr * vn;                                           \
        float nn = __fmaf_rn(2.f, fsig(2.f * aa), -1.f);                      \
        float hn = nn + zz * (hreg - nn);                                     \
        hreg = hn;                                                            \
        if (half == 0) {                                                      \
            (HW)[m] = hn;                                                     \
            __stcs(&outp[(size_t)(T_) * (Gn * Hn)], hn);                      \
        }                                                                     \
    }

    for (int t = 0; t < Tn; t += 2) {
        STEP2(hb0, hb1, t, xf0, xn0);
        {
            size_t o = (size_t)min(t + 2, Tn - 1) * 192;
            xf0 = __ldcs(xf_p + o);
            xn0 = __ldcs(xn_p + o);
        }
        STEP2(hb1, hb0, t + 1, xf1, xn1);
        {
            size_t o = (size_t)min(t + 3, Tn - 1) * 192;
            xf1 = __ldcs(xf_p + o);
            xn1 = __ldcs(xn_p + o);
        }
    }
#undef STEP2
#undef IBAR

    if (half == 0) {
        out[(size_t)Bn * Tn * (Gn * Hn) + ((size_t)g * Bn + b) * Hn + m] = hreg;
    }
}

// ---------------------------------------------------------------------------
extern "C" void kernel_launch(void* const* d_in, const int* in_sizes, int n_in,
                              void* d_out, int out_size)
{
    const float* x   = (const float*)d_in[0];
    const float* h0  = (const float*)d_in[1];
    const float* Wih = (const float*)d_in[2];
    const float* Whh = (const float*)d_in[3];
    const float* bih = (const float*)d_in[4];
    const float* bhh = (const float*)d_in[5];
    float* out = (float*)d_out;

    dim3 g1(ROWS / 64, Gn, 3);
    xproj_kernel<<<g1, 256>>>(x, Wih, bih);

    scan_kernel<<<(Bn / 2) * Gn, 256>>>(h0, Whh, bhh, out);
}

// round 8
// speedup vs baseline: 1.3014x; 1.0935x over previous
#include <cuda_runtime.h>
#include <math.h>
#include <stdint.h>

#define Gn 8
#define Hn 64
#define In 64
#define Bn 32
#define Tn 1000
#define XSTR (Gn * In)   // 512 floats per (b,t)

// ---------------- packed f32x2 helpers (sm_103a) ----------------
__device__ __forceinline__ uint64_t ffma2(uint64_t a, uint64_t b, uint64_t c) {
    uint64_t d;
    asm("fma.rn.f32x2 %0, %1, %2, %3;" : "=l"(d) : "l"(a), "l"(b), "l"(c));
    return d;
}
__device__ __forceinline__ uint64_t fadd2(uint64_t a, uint64_t b) {
    uint64_t d;
    asm("add.rn.f32x2 %0, %1, %2;" : "=l"(d) : "l"(a), "l"(b));
    return d;
}
__device__ __forceinline__ uint64_t pack2(float lo, float hi) {
    uint64_t d;
    asm("mov.b64 %0, {%1, %2};" : "=l"(d) : "f"(lo), "f"(hi));
    return d;
}
__device__ __forceinline__ float2 unpack2(uint64_t v) {
    float lo, hi;
    asm("mov.b64 {%0, %1}, %2;" : "=f"(lo), "=f"(hi) : "l"(v));
    return make_float2(lo, hi);
}
__device__ __forceinline__ float fsig(float x) {
    return __fdividef(1.f, 1.f + __expf(-x));
}

// 64-wide dot: w = 16 ulonglong2 (32 packed f32 pairs = 64 floats),
// v = 64 floats in smem (16B aligned), seeded in chain 0's low half.
__device__ __forceinline__ float dot64(const ulonglong2* w, const float* v, float seed) {
    const ulonglong2* v2 = (const ulonglong2*)v;   // 16 ulonglong2 = 64 floats
    uint64_t a0 = pack2(seed, 0.f), a1 = 0ull, a2 = 0ull, a3 = 0ull;
#pragma unroll
    for (int q = 0; q < 16; q += 2) {
        ulonglong2 va = v2[q];
        ulonglong2 vb = v2[q + 1];
        a0 = ffma2(w[q].x,     va.x, a0);
        a1 = ffma2(w[q].y,     va.y, a1);
        a2 = ffma2(w[q + 1].x, vb.x, a2);
        a3 = ffma2(w[q + 1].y, vb.y, a3);
    }
    float2 f = unpack2(fadd2(fadd2(a0, a1), fadd2(a2, a3)));
    return f.x + f.y;
}

// ---------------------------------------------------------------------------
// Fully fused GRU: one block per (b,g); 192 threads. Thread j owns BOTH
// Whh gate-row j (critical recurrent dot) and Wih gate-row j (input
// projection for step t+2, computed in the latency bubbles).
// x streams through a 4-slot smem ring (16 loader threads, 6-step lead);
// xp results flow through a 4-slot smem ring to the gate threads (j<64).
// grid = 256, block = 192, 2 blocks/SM (single wave)
// ---------------------------------------------------------------------------
__global__ void __launch_bounds__(192, 2) gru_fused_kernel(
    const float* __restrict__ x,
    const float* __restrict__ h0,
    const float* __restrict__ Wih,
    const float* __restrict__ Whh,
    const float* __restrict__ bih,
    const float* __restrict__ bhh,
    float* __restrict__ out)
{
    const int b = blockIdx.x >> 3;
    const int g = blockIdx.x & 7;
    const int j = threadIdx.x;

    __shared__ __align__(16) float h_sh[64];
    __shared__ __align__(16) float gh_sh[192];
    __shared__ __align__(16) float xq_sh[4][192];
    __shared__ __align__(16) float x_sh[4][64];

    // Both weight rows in registers: 2 x 16 ulonglong2 = 2 x 64 floats
    ulonglong2 whh_[16], wih_[16];
    {
        const ulonglong2* p = (const ulonglong2*)&Whh[((size_t)g * 192 + j) * Hn];
#pragma unroll
        for (int q = 0; q < 16; q++) whh_[q] = p[q];
        p = (const ulonglong2*)&Wih[((size_t)g * 192 + j) * In];
#pragma unroll
        for (int q = 0; q < 16; q++) wih_[q] = p[q];
    }
    const float bhj = bhh[g * 192 + j];
    const float bij = bih[g * 192 + j];

    const float* xsrc = x + ((size_t)b * Tn) * XSTR + g * In;

    const int  lj     = j - 128;
    const bool loader = ((unsigned)lj < 16u);
    const bool gate   = (j < 64);

    // ---- prolog: fill x_sh[0..3] = x(0..3), init h ----
    float hreg = 0.f;
    if (gate) {
        hreg = h0[((size_t)g * Bn + b) * Hn + j];
        h_sh[j] = hreg;
#pragma unroll
        for (int s = 0; s < 4; s++) x_sh[s][j] = xsrc[(size_t)s * XSTR + j];
    }
    __syncthreads();

    // xp(0), xp(1) into the xq ring; loaders stage x(4), x(5)
    xq_sh[0][j] = dot64(wih_, x_sh[0], bij);
    xq_sh[1][j] = dot64(wih_, x_sh[1], bij);
    float4 xa4 = make_float4(0.f, 0.f, 0.f, 0.f);
    float4 xb4 = xa4;
    if (loader) {
        xa4 = *(const float4*)&xsrc[(size_t)4 * XSTR + lj * 4];
        xb4 = *(const float4*)&xsrc[(size_t)5 * XSTR + lj * 4];
    }
    float* outp = out + (size_t)b * Tn * (Gn * Hn) + g * Hn + j;  // gates only
    __syncthreads();

#define STEP(T_, XREG_)                                                       \
    {                                                                         \
        /* phase A: critical recurrent dot + bubble-filling input dot */      \
        float ghv = dot64(whh_, h_sh, bhj);                                   \
        gh_sh[j] = ghv;                                                       \
        if ((T_) + 2 < Tn) {                                                  \
            int sl = ((T_) + 2) & 3;                                          \
            xq_sh[sl][j] = dot64(wih_, x_sh[sl], bij);                        \
        }                                                                     \
        if (loader) {                                                         \
            *(float4*)&x_sh[((T_) + 4) & 3][lj * 4] = XREG_;                  \
        }                                                                     \
        __syncthreads();                                                      \
        /* phase B: gates + output; loaders fetch x(t+6) */                   \
        if (gate) {                                                           \
            const float* xq = xq_sh[(T_) & 3];                                \
            float rr = fsig(xq[j]      + gh_sh[j]);                           \
            float zz = fsig(xq[64 + j] + gh_sh[64 + j]);                      \
            float aa = xq[128 + j] + rr * gh_sh[128 + j];                     \
            float nn = __fmaf_rn(2.f, fsig(2.f * aa), -1.f);                  \
            float hn = nn + zz * (hreg - nn);                                 \
            hreg = hn;                                                        \
            h_sh[j] = hn;                                                     \
            __stcs(&outp[(size_t)(T_) * (Gn * Hn)], hn);                      \
        }                                                                     \
        if (loader) {                                                         \
            size_t tl = (size_t)min((T_) + 6, Tn - 1);                        \
            XREG_ = *(const float4*)&xsrc[tl * XSTR + lj * 4];                \
        }                                                                     \
        __syncthreads();                                                      \
    }

    for (int t = 0; t < Tn; t += 2) {
        STEP(t, xa4);
        STEP(t + 1, xb4);
    }
#undef STEP

    if (gate) {
        out[(size_t)Bn * Tn * (Gn * Hn) + ((size_t)g * Bn + b) * Hn + j] = hreg;
    }
}

// ---------------------------------------------------------------------------
extern "C" void kernel_launch(void* const* d_in, const int* in_sizes, int n_in,
                              void* d_out, int out_size)
{
    const float* x   = (const float*)d_in[0];
    const float* h0  = (const float*)d_in[1];
    const float* Wih = (const float*)d_in[2];
    const float* Whh = (const float*)d_in[3];
    const float* bih = (const float*)d_in[4];
    const float* bhh = (const float*)d_in[5];
    float* out = (float*)d_out;

    gru_fused_kernel<<<Bn * Gn, 192>>>(x, h0, Wih, Whh, bih, bhh, out);
}